// round 1
// baseline (speedup 1.0000x reference)
#include <cuda_runtime.h>
#include <cstdint>

// Hierarchical polarization:
//   Z: (8, 16384, 256) fp32.  14 levels. Level L: groups of 2^(L+1), group mean ->
//   MLP (256->32 GELU 32->256) -> add back to every element of the group.
//
// Restructure:
//   P_0 = pairwise means of Z (never re-read Z in the level loop)
//   P_{L+1}[G] = 0.5*((P_L[2G]+At_L[2G]) + (P_L[2G+1]+At_L[2G+1]))
//   out = Z + sum_L At_L[group_of(s, L)]   (flat gather over the At pyramid)

#define LK_ROWS 32   // P-rows per block in the level kernel

// Scratch (device globals; no allocation allowed)
__device__ float4 g_P4[2][4194304];   // ping-pong P buffers, 64 MiB each
__device__ float4 g_At4[8388096];     // At pyramid, all 14 levels, 128 MiB total

__device__ __forceinline__ float gelu_tanh(float x) {
    // jax.nn.gelu default: approximate=True (tanh form)
    float x3 = x * x * x;
    float u  = 0.7978845608028654f * (x + 0.044715f * x3);
    return 0.5f * x * (1.0f + tanhf(u));
}

#define XS(r, d) (((float*)Xs4)[(r) * 256 + (d)])

// One polarization level: reads 32 P-rows (or computes them as pair-means of Z
// for level 0), runs the MLP per row, writes At rows, and emits 16 next-level
// P-rows (pairwise means of x+At).
__global__ void __launch_bounds__(256) level_kernel(
    const float4* __restrict__ Zsrc,   // Z, used only when ping < 0
    int ping,                          // -1: src=Z, out=g_P4[0]; else src=g_P4[ping], out=g_P4[ping^1]
    long long atOff,                   // float offset into At pyramid for this level
    int rows,                          // number of P-rows at this level (8 * n_groups)
    const float* __restrict__ W1, const float* __restrict__ b1,
    const float* __restrict__ W2, const float* __restrict__ b2)
{
    __shared__ float4 Xs4[LK_ROWS][64];     // 32 rows x 256 floats
    __shared__ float  Hs[LK_ROWS][32];

    const int t        = threadIdx.x;
    const int rowStart = blockIdx.x * LK_ROWS;

    float* Pout = (float*)g_P4[(ping < 0) ? 0 : (ping ^ 1)];
    float* At   = ((float*)g_At4) + atOff;

    // ---- load 32 rows into smem ----
    if (ping < 0) {
        // level 0: pair-means straight from Z. P0 row ro <-> Z rows 2ro, 2ro+1.
        #pragma unroll
        for (int k = 0; k < 8; k++) {
            int idx = t + 256 * k;            // 0..2047
            int r   = idx >> 6;
            int d4  = idx & 63;
            long long ro = rowStart + r;
            float4 a = Zsrc[ro * 128 + d4];
            float4 b = Zsrc[ro * 128 + 64 + d4];
            float4 v;
            v.x = 0.5f * (a.x + b.x); v.y = 0.5f * (a.y + b.y);
            v.z = 0.5f * (a.z + b.z); v.w = 0.5f * (a.w + b.w);
            Xs4[r][d4] = v;
        }
    } else {
        const float4* src = (const float4*)g_P4[ping];
        #pragma unroll
        for (int k = 0; k < 8; k++) {
            int idx = t + 256 * k;
            int r   = idx >> 6;
            int d4  = idx & 63;
            float4 v = make_float4(0.f, 0.f, 0.f, 0.f);
            if (rowStart + r < rows) v = src[(long long)(rowStart + r) * 64 + d4];
            Xs4[r][d4] = v;
        }
    }
    __syncthreads();

    // ---- phase 1: h = gelu(x @ W1 + b1).  Warp wp owns rows wp*4..wp*4+3, lane = j.
    const int lane = t & 31;
    const int wp   = t >> 5;
    const int r0   = wp * 4;
    {
        float a0 = 0.f, a1 = 0.f, a2 = 0.f, a3 = 0.f;
        #pragma unroll 16
        for (int d = 0; d < 256; d++) {
            float w = W1[d * 32 + lane];           // coalesced, L1-resident (32 KB)
            a0 = fmaf(XS(r0 + 0, d), w, a0);
            a1 = fmaf(XS(r0 + 1, d), w, a1);
            a2 = fmaf(XS(r0 + 2, d), w, a2);
            a3 = fmaf(XS(r0 + 3, d), w, a3);
        }
        float bb = b1[lane];
        Hs[r0 + 0][lane] = gelu_tanh(a0 + bb);
        Hs[r0 + 1][lane] = gelu_tanh(a1 + bb);
        Hs[r0 + 2][lane] = gelu_tanh(a2 + bb);
        Hs[r0 + 3][lane] = gelu_tanh(a3 + bb);
    }
    __syncwarp();   // Hs rows r0..r0+3 are produced and consumed by this warp only

    // ---- phase 3: At = h @ W2 + b2; write At; Xs += At ----
    #pragma unroll
    for (int k = 0; k < 8; k++) {
        int d = lane + 32 * k;
        float bv = b2[d];
        float a0 = bv, a1 = bv, a2 = bv, a3 = bv;
        #pragma unroll
        for (int j = 0; j < 32; j++) {
            float w = W2[j * 256 + d];             // coalesced, L1-resident
            a0 = fmaf(Hs[r0 + 0][j], w, a0);
            a1 = fmaf(Hs[r0 + 1][j], w, a1);
            a2 = fmaf(Hs[r0 + 2][j], w, a2);
            a3 = fmaf(Hs[r0 + 3][j], w, a3);
        }
        long long gr = rowStart + r0;
        if (gr + 0 < rows) At[(gr + 0) * 256 + d] = a0;
        if (gr + 1 < rows) At[(gr + 1) * 256 + d] = a1;
        if (gr + 2 < rows) At[(gr + 2) * 256 + d] = a2;
        if (gr + 3 < rows) At[(gr + 3) * 256 + d] = a3;
        XS(r0 + 0, d) += a0;
        XS(r0 + 1, d) += a1;
        XS(r0 + 2, d) += a2;
        XS(r0 + 3, d) += a3;
    }
    __syncthreads();

    // ---- phase 4: next-level P rows = pairwise means of (x + At) ----
    #pragma unroll
    for (int k = 0; k < 16; k++) {
        int idx = t + 256 * k;        // 0..4095
        int pr  = idx >> 8;           // 0..15 pair within block
        int d   = idx & 255;
        int gp  = blockIdx.x * (LK_ROWS / 2) + pr;
        if (2 * gp + 1 < rows)
            Pout[(long long)gp * 256 + d] =
                0.5f * (XS(2 * pr, d) + XS(2 * pr + 1, d));
    }
}

// out = Z + sum over 14 levels of At[level][b, s>>(L+1), d]
__global__ void __launch_bounds__(256) final_kernel(
    const float4* __restrict__ Z4, float4* __restrict__ out4)
{
    int i   = blockIdx.x * 256 + threadIdx.x;  // < 8388608 float4 elements
    int d4  = i & 63;
    int row = i >> 6;          // b*16384 + s
    int b   = row >> 14;
    int s   = row & 16383;

    float4 acc = Z4[i];
    long long off4 = 0;        // float4 offset into pyramid
    int ng = 8192;
    #pragma unroll
    for (int L = 0; L < 14; L++) {
        int g = s >> (L + 1);
        float4 a = g_At4[off4 + (long long)(b * ng + g) * 64 + d4];
        acc.x += a.x; acc.y += a.y; acc.z += a.z; acc.w += a.w;
        off4 += 512LL * ng;    // 8*ng*256 floats / 4
        ng >>= 1;
    }
    out4[i] = acc;
}

extern "C" void kernel_launch(void* const* d_in, const int* in_sizes, int n_in,
                              void* d_out, int out_size)
{
    const float* Z  = (const float*)d_in[0];
    const float* W1 = (const float*)d_in[1];
    const float* b1 = (const float*)d_in[2];
    const float* W2 = (const float*)d_in[3];
    const float* b2 = (const float*)d_in[4];

    long long atOff = 0;
    int ng = 8192;                       // groups at level 0 per batch
    for (int L = 0; L < 14; L++) {
        int rows   = 8 * ng;             // batch * n_groups
        int tt     = (L < 10) ? L : 9;   // transform index = min(level, 9)
        int ping   = (L == 0) ? -1 : ((L - 1) & 1);
        int blocks = (rows + LK_ROWS - 1) / LK_ROWS;
        level_kernel<<<blocks, 256>>>((const float4*)Z, ping, atOff, rows,
                                      W1 + (long long)tt * 8192,
                                      b1 + tt * 32,
                                      W2 + (long long)tt * 8192,
                                      b2 + tt * 256);
        atOff += (long long)rows * 256;
        ng >>= 1;
    }
    final_kernel<<<32768, 256>>>((const float4*)Z, (float4*)d_out);
}